// round 15
// baseline (speedup 1.0000x reference)
#include <cuda_runtime.h>
#include <cuda_fp16.h>
#include <math.h>
#include <stdint.h>

// ---------------- problem constants ----------------
#define B_SZ   64
#define T_SZ   512
#define D_IN   968
#define HID    128
#define G3     384
#define MROWS  (B_SZ * T_SZ)      // 32768
#define KPAD   992                // D_IN padded to 31*32 (was 1024)
#define NTOT   768

// ---------------- scratch ----------------
__device__ float g_xp[2u * MROWS * G3];
__device__ __half g_abf[(size_t)MROWS * KPAD];
__device__ __half g_wbf[(size_t)NTOT * KPAD];

// ---------------- helpers ----------------
__device__ __forceinline__ uint32_t smem_u32(const void* p) {
    uint32_t a;
    asm("{ .reg .u64 t; cvta.to.shared.u64 t, %1; cvt.u32.u64 %0, t; }" : "=r"(a) : "l"(p));
    return a;
}
__device__ __forceinline__ void cp16(uint32_t dst, const void* src) {
    asm volatile("cp.async.cg.shared.global [%0], [%1], 16;" :: "r"(dst), "l"(src));
}
__device__ __forceinline__ void cp_commit() {
    asm volatile("cp.async.commit_group;" ::: "memory");
}
__device__ __forceinline__ void cp_wait1() {
    asm volatile("cp.async.wait_group 1;" ::: "memory");
}
__device__ __forceinline__ void ldmx4(uint32_t* r, uint32_t a) {
    asm volatile("ldmatrix.sync.aligned.m8n8.x4.shared.b16 {%0,%1,%2,%3}, [%4];"
                 : "=r"(r[0]), "=r"(r[1]), "=r"(r[2]), "=r"(r[3]) : "r"(a));
}
__device__ __forceinline__ void mma_f16(float* c, const uint32_t* a, const uint32_t* b) {
    asm volatile("mma.sync.aligned.m16n8k16.row.col.f32.f16.f16.f32 "
                 "{%0,%1,%2,%3}, {%4,%5,%6,%7}, {%8,%9}, {%0,%1,%2,%3};"
                 : "+f"(c[0]), "+f"(c[1]), "+f"(c[2]), "+f"(c[3])
                 : "r"(a[0]), "r"(a[1]), "r"(a[2]), "r"(a[3]), "r"(b[0]), "r"(b[1]));
}
__device__ __forceinline__ unsigned long long fma2(unsigned long long a,
                                                   unsigned long long b,
                                                   unsigned long long c) {
    unsigned long long d;
    asm("fma.rn.f32x2 %0, %1, %2, %3;" : "=l"(d) : "l"(a), "l"(b), "l"(c));
    return d;
}
__device__ __forceinline__ unsigned long long add2(unsigned long long a,
                                                   unsigned long long b) {
    unsigned long long d;
    asm("add.rn.f32x2 %0, %1, %2;" : "=l"(d) : "l"(a), "l"(b));
    return d;
}
__device__ __forceinline__ unsigned long long pack2(float x, float y) {
    float2 t = make_float2(x, y);
    return *(unsigned long long*)&t;
}
__device__ __forceinline__ float fast_sigmoid(float x) {
    return __fdividef(1.f, 1.f + __expf(-x));
}
__device__ __forceinline__ float fast_tanh(float y) {
    const float e = __expf(-2.f * fabsf(y));
    const float n = __fdividef(1.f - e, 1.f + e);
    return copysignf(n, y);
}

// =================================================================
// Kernel 0: fp32 -> fp16, x and w merged into one launch.
//   blocks [0, MROWS)          -> x rows   -> g_abf
//   blocks [MROWS, MROWS+NTOT) -> w rows   -> g_wbf
// =================================================================
__global__ __launch_bounds__(128) void conv_all(const float* __restrict__ x,
                                                const float* __restrict__ w_f,
                                                const float* __restrict__ w_b) {
    const int rb = blockIdx.x;
    const float* src;
    __half* dst;
    if (rb < MROWS) {
        src = x + (size_t)rb * D_IN;
        dst = g_abf + (size_t)rb * KPAD;
    } else {
        const int n = rb - MROWS;
        src = (n < G3) ? (w_f + (size_t)n * D_IN) : (w_b + (size_t)(n - G3) * D_IN);
        dst = g_wbf + (size_t)n * KPAD;
    }
    const int k = threadIdx.x * 8;
    if (k >= KPAD) return;
    const float* s = src + k;
    __half2 h[4];
    if (k + 8 <= D_IN) {
        float4 v0 = *(const float4*)(s);
        float4 v1 = *(const float4*)(s + 4);
        h[0] = __floats2half2_rn(v0.x, v0.y);
        h[1] = __floats2half2_rn(v0.z, v0.w);
        h[2] = __floats2half2_rn(v1.x, v1.y);
        h[3] = __floats2half2_rn(v1.z, v1.w);
    } else {
        float t[8];
#pragma unroll
        for (int q = 0; q < 8; q++) t[q] = (k + q < D_IN) ? s[q] : 0.f;
        h[0] = __floats2half2_rn(t[0], t[1]);
        h[1] = __floats2half2_rn(t[2], t[3]);
        h[2] = __floats2half2_rn(t[4], t[5]);
        h[3] = __floats2half2_rn(t[6], t[7]);
    }
    *(uint4*)(dst + k) = *(uint4*)h;
}

// =================================================================
// Kernel 1: HMMA fp16 GEMM.  M=32768, N=768, K=992 (31 stages).
//   CTA 128x128x32, 8 warps, 3-stage cp.async, single
//   __syncthreads per stage, 2 CTAs/SM.
// =================================================================
#define BK      32
#define ROWB    80
#define ATILE   (128 * ROWB)
#define STAGEB  (2 * ATILE)
#define NSTG    31
#define GEMM_SMEM (3 * STAGEB)   // 61440

__global__ __launch_bounds__(256, 2) void gemm_mma(const float* __restrict__ bias_f,
                                                   const float* __restrict__ bias_b) {
    extern __shared__ char smem[];
    const uint32_t sb = smem_u32(smem);
    const int tid  = threadIdx.x;
    const int wid  = tid >> 5;
    const int lane = tid & 31;
    const int wrow = wid >> 2;
    const int wcol = wid & 3;

    const int m0 = blockIdx.y * 128;
    const int n0 = blockIdx.x * 128;

    const __half* Ag = g_abf + (size_t)m0 * KPAD;
    const __half* Bg = g_wbf + (size_t)n0 * KPAD;

    const int lrow  = tid >> 1;
    const int lseg0 = (tid & 1) * 2;

    float acc[4][4][4];
#pragma unroll
    for (int i = 0; i < 4; i++)
#pragma unroll
        for (int j = 0; j < 4; j++)
#pragma unroll
            for (int q = 0; q < 4; q++) acc[i][j][q] = 0.f;

    auto issue = [&](int s) {
        const int k0 = s * BK;
        const uint32_t st = sb + (s % 3) * STAGEB;
        const __half* arow = Ag + (size_t)lrow * KPAD + k0;
        const __half* brow = Bg + (size_t)lrow * KPAD + k0;
        cp16(st + lrow * ROWB + lseg0 * 16,        arow + lseg0 * 8);
        cp16(st + lrow * ROWB + (lseg0 + 1) * 16,  arow + (lseg0 + 1) * 8);
        cp16(st + ATILE + lrow * ROWB + lseg0 * 16,       brow + lseg0 * 8);
        cp16(st + ATILE + lrow * ROWB + (lseg0 + 1) * 16, brow + (lseg0 + 1) * 8);
    };

    issue(0); cp_commit();
    issue(1); cp_commit();

    const int a_r = (lane & 15);
    const int a_c = (lane >> 4) * 16;
    const int b_r = (lane & 7) + ((lane >> 4) << 3);
    const int b_c = ((lane >> 3) & 1) * 16;

    for (int s = 0; s < NSTG; s++) {
        cp_wait1();
        __syncthreads();   // all warps done with compute(s-1) = buffer (s+2)%3
        if (s + 2 < NSTG) issue(s + 2);
        cp_commit();

        const uint32_t st = sb + (s % 3) * STAGEB;
        const uint32_t aw = st + (wrow * 64 + a_r) * ROWB + a_c;
        const uint32_t bw = st + ATILE + (wcol * 32 + b_r) * ROWB + b_c;

#pragma unroll
        for (int kh = 0; kh < 2; kh++) {
            uint32_t afr[4][4], bfr[2][4];
#pragma unroll
            for (int mf = 0; mf < 4; mf++)
                ldmx4(afr[mf], aw + mf * 16 * ROWB + kh * 32);
#pragma unroll
            for (int np = 0; np < 2; np++)
                ldmx4(bfr[np], bw + np * 16 * ROWB + kh * 32);
#pragma unroll
            for (int mf = 0; mf < 4; mf++) {
#pragma unroll
                for (int nf = 0; nf < 4; nf++) {
                    uint32_t bp[2];
                    bp[0] = bfr[nf >> 1][(nf & 1) * 2 + 0];
                    bp[1] = bfr[nf >> 1][(nf & 1) * 2 + 1];
                    mma_f16(acc[mf][nf], afr[mf], bp);
                }
            }
        }
    }

    const int dir = (n0 >= G3) ? 1 : 0;
    const int gbase = n0 - dir * G3;
    const float* bias = dir ? bias_b : bias_f;

#pragma unroll
    for (int mf = 0; mf < 4; mf++) {
#pragma unroll
        for (int nf = 0; nf < 4; nf++) {
            const int g = gbase + wcol * 32 + nf * 8 + (lane & 3) * 2;
            const float bx = bias[g], by = bias[g + 1];
            const int r0 = m0 + wrow * 64 + mf * 16 + (lane >> 2);
            float* d0 = g_xp + ((size_t)dir * MROWS + r0) * G3 + g;
            float* d1 = d0 + (size_t)8 * G3;
            *(float2*)d0 = make_float2(acc[mf][nf][0] + bx, acc[mf][nf][1] + by);
            *(float2*)d1 = make_float2(acc[mf][nf][2] + bx, acc[mf][nf][3] + by);
        }
    }
}

// =================================================================
// Kernel 2: GRU scan — R6/R8/R14 kernel, three-run-reproducible 355us.
//   384 threads, one gate-row/thread, weights in regs, sigmoids in
//   phase A, phase B on n-gate group, 2-step gi prefetch.
// =================================================================
__global__ __launch_bounds__(384, 1) void gru_scan(
    const float* __restrict__ w_hh_f, const float* __restrict__ w_hh_b,
    const float* __restrict__ b_hh_f, const float* __restrict__ b_hh_b,
    float* __restrict__ out)
{
    __shared__ float4 h4s[32];            // h vector (float4 view)
    __shared__ float sR[128];             // sigmoid(r)
    __shared__ float sZ[128];             // sigmoid(z)

    const int j   = threadIdx.x;
    const int g   = j >> 7;               // 0=r 1=z 2=n
    const int i   = j & 127;
    const int dir = blockIdx.x & 1;
    const int b   = blockIdx.x >> 1;

    const float* __restrict__ w  = dir ? w_hh_b : w_hh_f;
    const float* __restrict__ bh = dir ? b_hh_b : b_hh_f;

    unsigned long long wp[64];
    const float4* wrow = (const float4*)(w + (size_t)j * HID);
#pragma unroll
    for (int q = 0; q < 32; q++) {
        float4 v = wrow[q];
        wp[2 * q]     = pack2(v.x, v.y);
        wp[2 * q + 1] = pack2(v.z, v.w);
    }
    const float bj = bh[j];
    if (j < 32) h4s[j] = make_float4(0.f, 0.f, 0.f, 0.f);
    __syncthreads();

    const float* xp_base  = g_xp + ((size_t)dir * MROWS + (size_t)b * T_SZ) * G3;
    float*       out_base = out + (size_t)b * T_SZ * 256 + dir * HID;
    const int t0 = dir ? (T_SZ - 1) : 0;
    const int tstep = dir ? -1 : 1;

    float hprev = 0.f;
    float gi0 = xp_base[(size_t)t0 * G3 + j];
    float gi1 = (T_SZ > 1) ? xp_base[(size_t)(t0 + tstep) * G3 + j] : 0.f;

    int t = t0;
    for (int s = 0; s < T_SZ; s++) {
        float gi2 = 0.f;
        if (s + 2 < T_SZ) gi2 = xp_base[(size_t)(t + 2 * tstep) * G3 + j];

        // ---- phase A: dot(w_j, h) via LDS.128 broadcast, 4 chains ----
        unsigned long long a0 = 0ull, a1 = 0ull, a2 = 0ull, a3 = 0ull;
#pragma unroll
        for (int q = 0; q < 8; q++) {
            float4 v0 = h4s[4 * q + 0];
            float4 v1 = h4s[4 * q + 1];
            float4 v2 = h4s[4 * q + 2];
            float4 v3 = h4s[4 * q + 3];
            a0 = fma2(wp[8 * q + 0], pack2(v0.x, v0.y), a0);
            a0 = fma2(wp[8 * q + 1], pack2(v0.z, v0.w), a0);
            a1 = fma2(wp[8 * q + 2], pack2(v1.x, v1.y), a1);
            a1 = fma2(wp[8 * q + 3], pack2(v1.z, v1.w), a1);
            a2 = fma2(wp[8 * q + 4], pack2(v2.x, v2.y), a2);
            a2 = fma2(wp[8 * q + 5], pack2(v2.z, v2.w), a2);
            a3 = fma2(wp[8 * q + 6], pack2(v3.x, v3.y), a3);
            a3 = fma2(wp[8 * q + 7], pack2(v3.z, v3.w), a3);
        }
        a0 = add2(a0, a1);
        a2 = add2(a2, a3);
        a0 = add2(a0, a2);
        float2 ap = *(float2*)&a0;
        const float accv = ap.x + ap.y + bj;

        if (g == 0)      sR[i] = fast_sigmoid(accv + gi0);
        else if (g == 1) sZ[i] = fast_sigmoid(accv + gi0);
        // g==2 keeps gh_n=accv, gi_n=gi0 in registers

        __syncthreads();

        // ---- phase B: n-gate group updates h ----
        if (g == 2) {
            const float r = sR[i];
            const float z = sZ[i];
            const float n = fast_tanh(fmaf(r, accv, gi0));
            const float hn = fmaf(z, hprev - n, n);
            hprev = hn;
            ((float*)h4s)[i] = hn;
            out_base[(size_t)t * 256 + i] = hn;
        }
        __syncthreads();

        gi0 = gi1;
        gi1 = gi2;
        t += tstep;
    }
}

// =================================================================
// Kernel 3: LayerNorm (ddof=1 std, clamp 1e-6), in place
// =================================================================
__global__ __launch_bounds__(256) void layernorm_rows(
    float* __restrict__ out, const float* __restrict__ ln_w, const float* __restrict__ ln_b)
{
    const size_t row = blockIdx.x;
    const int c = threadIdx.x;
    float* p = out + row * 256;
    const float v = p[c];

    float s = v, ss = v * v;
#pragma unroll
    for (int o = 16; o > 0; o >>= 1) {
        s  += __shfl_xor_sync(0xffffffffu, s, o);
        ss += __shfl_xor_sync(0xffffffffu, ss, o);
    }
    __shared__ float rs[8], rss[8];
    const int wid = c >> 5, lid = c & 31;
    if (lid == 0) { rs[wid] = s; rss[wid] = ss; }
    __syncthreads();
    if (c < 32) {
        s  = (lid < 8) ? rs[lid]  : 0.f;
        ss = (lid < 8) ? rss[lid] : 0.f;
#pragma unroll
        for (int o = 4; o > 0; o >>= 1) {
            s  += __shfl_xor_sync(0xffffffffu, s, o);
            ss += __shfl_xor_sync(0xffffffffu, ss, o);
        }
        if (lid == 0) { rs[0] = s; rss[0] = ss; }
    }
    __syncthreads();
    s = rs[0]; ss = rss[0];

    const float mu  = s * (1.f / 256.f);
    float var = (ss - 256.f * mu * mu) * (1.f / 255.f);
    float sig = sqrtf(fmaxf(var, 0.f));
    sig = fmaxf(sig, 1e-6f);
    p[c] = (v - mu) / sig * ln_w[c] + ln_b[c];
}

// =================================================================
// launch
// =================================================================
extern "C" void kernel_launch(void* const* d_in, const int* in_sizes, int n_in,
                              void* d_out, int out_size)
{
    const float* x      = (const float*)d_in[0];
    const float* w_ih_f = (const float*)d_in[1];
    const float* w_hh_f = (const float*)d_in[2];
    const float* b_ih_f = (const float*)d_in[3];
    const float* b_hh_f = (const float*)d_in[4];
    const float* w_ih_b = (const float*)d_in[5];
    const float* w_hh_b = (const float*)d_in[6];
    const float* b_ih_b = (const float*)d_in[7];
    const float* b_hh_b = (const float*)d_in[8];
    const float* ln_w   = (const float*)d_in[9];
    const float* ln_b   = (const float*)d_in[10];
    float* out = (float*)d_out;

    static bool attrs_set = []() {
        cudaFuncSetAttribute(gemm_mma, cudaFuncAttributeMaxDynamicSharedMemorySize, GEMM_SMEM);
        return true;
    }();
    (void)attrs_set;

    conv_all<<<MROWS + NTOT, 128>>>(x, w_ih_f, w_ih_b);

    dim3 ggrid(NTOT / 128, MROWS / 128);   // (6, 256)
    gemm_mma<<<ggrid, 256, GEMM_SMEM>>>(b_ih_f, b_ih_b);

    gru_scan<<<B_SZ * 2, 384>>>(w_hh_f, w_hh_b, b_hh_f, b_hh_b, out);

    layernorm_rows<<<MROWS, 256>>>(out, ln_w, ln_b);
}

// round 16
// speedup vs baseline: 1.0620x; 1.0620x over previous
#include <cuda_runtime.h>
#include <cuda_fp16.h>
#include <math.h>
#include <stdint.h>

// ---------------- problem constants ----------------
#define B_SZ   64
#define T_SZ   512
#define D_IN   968
#define HID    128
#define G3     384
#define MROWS  (B_SZ * T_SZ)      // 32768
#define KPAD   1024
#define NTOT   768

// ---------------- scratch ----------------
__device__ float g_xp[2u * MROWS * G3];
__device__ __half g_abf[(size_t)MROWS * KPAD];
__device__ __half g_wbf[(size_t)NTOT * KPAD];

// ---------------- helpers ----------------
__device__ __forceinline__ uint32_t smem_u32(const void* p) {
    uint32_t a;
    asm("{ .reg .u64 t; cvta.to.shared.u64 t, %1; cvt.u32.u64 %0, t; }" : "=r"(a) : "l"(p));
    return a;
}
__device__ __forceinline__ void cp16(uint32_t dst, const void* src) {
    asm volatile("cp.async.cg.shared.global [%0], [%1], 16;" :: "r"(dst), "l"(src));
}
__device__ __forceinline__ void cp_commit() {
    asm volatile("cp.async.commit_group;" ::: "memory");
}
__device__ __forceinline__ void cp_wait1() {
    asm volatile("cp.async.wait_group 1;" ::: "memory");
}
__device__ __forceinline__ void ldmx4(uint32_t* r, uint32_t a) {
    asm volatile("ldmatrix.sync.aligned.m8n8.x4.shared.b16 {%0,%1,%2,%3}, [%4];"
                 : "=r"(r[0]), "=r"(r[1]), "=r"(r[2]), "=r"(r[3]) : "r"(a));
}
__device__ __forceinline__ void mma_f16(float* c, const uint32_t* a, const uint32_t* b) {
    asm volatile("mma.sync.aligned.m16n8k16.row.col.f32.f16.f16.f32 "
                 "{%0,%1,%2,%3}, {%4,%5,%6,%7}, {%8,%9}, {%0,%1,%2,%3};"
                 : "+f"(c[0]), "+f"(c[1]), "+f"(c[2]), "+f"(c[3])
                 : "r"(a[0]), "r"(a[1]), "r"(a[2]), "r"(a[3]), "r"(b[0]), "r"(b[1]));
}
__device__ __forceinline__ unsigned long long fma2(unsigned long long a,
                                                   unsigned long long b,
                                                   unsigned long long c) {
    unsigned long long d;
    asm("fma.rn.f32x2 %0, %1, %2, %3;" : "=l"(d) : "l"(a), "l"(b), "l"(c));
    return d;
}
__device__ __forceinline__ unsigned long long add2(unsigned long long a,
                                                   unsigned long long b) {
    unsigned long long d;
    asm("add.rn.f32x2 %0, %1, %2;" : "=l"(d) : "l"(a), "l"(b));
    return d;
}
__device__ __forceinline__ unsigned long long pack2(float x, float y) {
    float2 t = make_float2(x, y);
    return *(unsigned long long*)&t;
}
__device__ __forceinline__ float fast_sigmoid(float x) {
    return __fdividef(1.f, 1.f + __expf(-x));
}
__device__ __forceinline__ float fast_tanh(float y) {
    const float e = __expf(-2.f * fabsf(y));
    const float n = __fdividef(1.f - e, 1.f + e);
    return copysignf(n, y);
}

// =================================================================
// Kernel 0: fp32 -> fp16, vectorized (R11/R14 — measured best)
// =================================================================
__global__ __launch_bounds__(128) void conv_x(const float* __restrict__ x) {
    const int m = blockIdx.x;
    const int k = threadIdx.x * 8;
    const float* src = x + (size_t)m * D_IN + k;
    __half2 h[4];
    if (k + 8 <= D_IN) {
        float4 v0 = *(const float4*)(src);
        float4 v1 = *(const float4*)(src + 4);
        h[0] = __floats2half2_rn(v0.x, v0.y);
        h[1] = __floats2half2_rn(v0.z, v0.w);
        h[2] = __floats2half2_rn(v1.x, v1.y);
        h[3] = __floats2half2_rn(v1.z, v1.w);
    } else {
        float t[8];
#pragma unroll
        for (int q = 0; q < 8; q++) t[q] = (k + q < D_IN) ? src[q] : 0.f;
        h[0] = __floats2half2_rn(t[0], t[1]);
        h[1] = __floats2half2_rn(t[2], t[3]);
        h[2] = __floats2half2_rn(t[4], t[5]);
        h[3] = __floats2half2_rn(t[6], t[7]);
    }
    *(uint4*)(g_abf + (size_t)m * KPAD + k) = *(uint4*)h;
}
__global__ __launch_bounds__(128) void conv_w(const float* __restrict__ w_f,
                                              const float* __restrict__ w_b) {
    const int n = blockIdx.x;
    const int k = threadIdx.x * 8;
    const float* src = ((n < G3) ? (w_f + (size_t)n * D_IN)
                                 : (w_b + (size_t)(n - G3) * D_IN)) + k;
    __half2 h[4];
    if (k + 8 <= D_IN) {
        float4 v0 = *(const float4*)(src);
        float4 v1 = *(const float4*)(src + 4);
        h[0] = __floats2half2_rn(v0.x, v0.y);
        h[1] = __floats2half2_rn(v0.z, v0.w);
        h[2] = __floats2half2_rn(v1.x, v1.y);
        h[3] = __floats2half2_rn(v1.z, v1.w);
    } else {
        float t[8];
#pragma unroll
        for (int q = 0; q < 8; q++) t[q] = (k + q < D_IN) ? src[q] : 0.f;
        h[0] = __floats2half2_rn(t[0], t[1]);
        h[1] = __floats2half2_rn(t[2], t[3]);
        h[2] = __floats2half2_rn(t[4], t[5]);
        h[3] = __floats2half2_rn(t[6], t[7]);
    }
    *(uint4*)(g_wbf + (size_t)n * KPAD + k) = *(uint4*)h;
}

// =================================================================
// Kernel 1: HMMA fp16 GEMM (R9/R14 config — measured best).
//   M=32768, N=768, K=1024.  CTA 128x128x32, 8 warps, 3-stage
//   cp.async, single __syncthreads per stage, 2 CTAs/SM.
// =================================================================
#define BK      32
#define ROWB    80
#define ATILE   (128 * ROWB)
#define STAGEB  (2 * ATILE)
#define NSTG    32
#define GEMM_SMEM (3 * STAGEB)   // 61440

__global__ __launch_bounds__(256, 2) void gemm_mma(const float* __restrict__ bias_f,
                                                   const float* __restrict__ bias_b) {
    extern __shared__ char smem[];
    const uint32_t sb = smem_u32(smem);
    const int tid  = threadIdx.x;
    const int wid  = tid >> 5;
    const int lane = tid & 31;
    const int wrow = wid >> 2;
    const int wcol = wid & 3;

    const int m0 = blockIdx.y * 128;
    const int n0 = blockIdx.x * 128;

    const __half* Ag = g_abf + (size_t)m0 * KPAD;
    const __half* Bg = g_wbf + (size_t)n0 * KPAD;

    const int lrow  = tid >> 1;
    const int lseg0 = (tid & 1) * 2;

    float acc[4][4][4];
#pragma unroll
    for (int i = 0; i < 4; i++)
#pragma unroll
        for (int j = 0; j < 4; j++)
#pragma unroll
            for (int q = 0; q < 4; q++) acc[i][j][q] = 0.f;

    auto issue = [&](int s) {
        const int k0 = s * BK;
        const uint32_t st = sb + (s % 3) * STAGEB;
        const __half* arow = Ag + (size_t)lrow * KPAD + k0;
        const __half* brow = Bg + (size_t)lrow * KPAD + k0;
        cp16(st + lrow * ROWB + lseg0 * 16,        arow + lseg0 * 8);
        cp16(st + lrow * ROWB + (lseg0 + 1) * 16,  arow + (lseg0 + 1) * 8);
        cp16(st + ATILE + lrow * ROWB + lseg0 * 16,       brow + lseg0 * 8);
        cp16(st + ATILE + lrow * ROWB + (lseg0 + 1) * 16, brow + (lseg0 + 1) * 8);
    };

    issue(0); cp_commit();
    issue(1); cp_commit();

    const int a_r = (lane & 15);
    const int a_c = (lane >> 4) * 16;
    const int b_r = (lane & 7) + ((lane >> 4) << 3);
    const int b_c = ((lane >> 3) & 1) * 16;

    for (int s = 0; s < NSTG; s++) {
        cp_wait1();
        __syncthreads();   // all warps done with compute(s-1) = buffer (s+2)%3
        if (s + 2 < NSTG) issue(s + 2);
        cp_commit();

        const uint32_t st = sb + (s % 3) * STAGEB;
        const uint32_t aw = st + (wrow * 64 + a_r) * ROWB + a_c;
        const uint32_t bw = st + ATILE + (wcol * 32 + b_r) * ROWB + b_c;

#pragma unroll
        for (int kh = 0; kh < 2; kh++) {
            uint32_t afr[4][4], bfr[2][4];
#pragma unroll
            for (int mf = 0; mf < 4; mf++)
                ldmx4(afr[mf], aw + mf * 16 * ROWB + kh * 32);
#pragma unroll
            for (int np = 0; np < 2; np++)
                ldmx4(bfr[np], bw + np * 16 * ROWB + kh * 32);
#pragma unroll
            for (int mf = 0; mf < 4; mf++) {
#pragma unroll
                for (int nf = 0; nf < 4; nf++) {
                    uint32_t bp[2];
                    bp[0] = bfr[nf >> 1][(nf & 1) * 2 + 0];
                    bp[1] = bfr[nf >> 1][(nf & 1) * 2 + 1];
                    mma_f16(acc[mf][nf], afr[mf], bp);
                }
            }
        }
    }

    const int dir = (n0 >= G3) ? 1 : 0;
    const int gbase = n0 - dir * G3;
    const float* bias = dir ? bias_b : bias_f;

#pragma unroll
    for (int mf = 0; mf < 4; mf++) {
#pragma unroll
        for (int nf = 0; nf < 4; nf++) {
            const int g = gbase + wcol * 32 + nf * 8 + (lane & 3) * 2;
            const float bx = bias[g], by = bias[g + 1];
            const int r0 = m0 + wrow * 64 + mf * 16 + (lane >> 2);
            float* d0 = g_xp + ((size_t)dir * MROWS + r0) * G3 + g;
            float* d1 = d0 + (size_t)8 * G3;
            *(float2*)d0 = make_float2(acc[mf][nf][0] + bx, acc[mf][nf][1] + by);
            *(float2*)d1 = make_float2(acc[mf][nf][2] + bx, acc[mf][nf][3] + by);
        }
    }
}

// =================================================================
// Kernel 2: GRU scan — R6/R8/R14 kernel (three-run-reproducible 355us).
// =================================================================
__global__ __launch_bounds__(384, 1) void gru_scan(
    const float* __restrict__ w_hh_f, const float* __restrict__ w_hh_b,
    const float* __restrict__ b_hh_f, const float* __restrict__ b_hh_b,
    float* __restrict__ out)
{
    __shared__ float4 h4s[32];            // h vector (float4 view)
    __shared__ float sR[128];             // sigmoid(r)
    __shared__ float sZ[128];             // sigmoid(z)

    const int j   = threadIdx.x;
    const int g   = j >> 7;               // 0=r 1=z 2=n
    const int i   = j & 127;
    const int dir = blockIdx.x & 1;
    const int b   = blockIdx.x >> 1;

    const float* __restrict__ w  = dir ? w_hh_b : w_hh_f;
    const float* __restrict__ bh = dir ? b_hh_b : b_hh_f;

    unsigned long long wp[64];
    const float4* wrow = (const float4*)(w + (size_t)j * HID);
#pragma unroll
    for (int q = 0; q < 32; q++) {
        float4 v = wrow[q];
        wp[2 * q]     = pack2(v.x, v.y);
        wp[2 * q + 1] = pack2(v.z, v.w);
    }
    const float bj = bh[j];
    if (j < 32) h4s[j] = make_float4(0.f, 0.f, 0.f, 0.f);
    __syncthreads();

    const float* xp_base  = g_xp + ((size_t)dir * MROWS + (size_t)b * T_SZ) * G3;
    float*       out_base = out + (size_t)b * T_SZ * 256 + dir * HID;
    const int t0 = dir ? (T_SZ - 1) : 0;
    const int tstep = dir ? -1 : 1;

    float hprev = 0.f;
    float gi0 = xp_base[(size_t)t0 * G3 + j];
    float gi1 = (T_SZ > 1) ? xp_base[(size_t)(t0 + tstep) * G3 + j] : 0.f;

    int t = t0;
    for (int s = 0; s < T_SZ; s++) {
        float gi2 = 0.f;
        if (s + 2 < T_SZ) gi2 = xp_base[(size_t)(t + 2 * tstep) * G3 + j];

        // ---- phase A: dot(w_j, h) via LDS.128 broadcast, 4 chains ----
        unsigned long long a0 = 0ull, a1 = 0ull, a2 = 0ull, a3 = 0ull;
#pragma unroll
        for (int q = 0; q < 8; q++) {
            float4 v0 = h4s[4 * q + 0];
            float4 v1 = h4s[4 * q + 1];
            float4 v2 = h4s[4 * q + 2];
            float4 v3 = h4s[4 * q + 3];
            a0 = fma2(wp[8 * q + 0], pack2(v0.x, v0.y), a0);
            a0 = fma2(wp[8 * q + 1], pack2(v0.z, v0.w), a0);
            a1 = fma2(wp[8 * q + 2], pack2(v1.x, v1.y), a1);
            a1 = fma2(wp[8 * q + 3], pack2(v1.z, v1.w), a1);
            a2 = fma2(wp[8 * q + 4], pack2(v2.x, v2.y), a2);
            a2 = fma2(wp[8 * q + 5], pack2(v2.z, v2.w), a2);
            a3 = fma2(wp[8 * q + 6], pack2(v3.x, v3.y), a3);
            a3 = fma2(wp[8 * q + 7], pack2(v3.z, v3.w), a3);
        }
        a0 = add2(a0, a1);
        a2 = add2(a2, a3);
        a0 = add2(a0, a2);
        float2 ap = *(float2*)&a0;
        const float accv = ap.x + ap.y + bj;

        if (g == 0)      sR[i] = fast_sigmoid(accv + gi0);
        else if (g == 1) sZ[i] = fast_sigmoid(accv + gi0);
        // g==2 keeps gh_n=accv, gi_n=gi0 in registers

        __syncthreads();

        // ---- phase B: n-gate group updates h ----
        if (g == 2) {
            const float r = sR[i];
            const float z = sZ[i];
            const float n = fast_tanh(fmaf(r, accv, gi0));
            const float hn = fmaf(z, hprev - n, n);
            hprev = hn;
            ((float*)h4s)[i] = hn;
            out_base[(size_t)t * 256 + i] = hn;
        }
        __syncthreads();

        gi0 = gi1;
        gi1 = gi2;
        t += tstep;
    }
}

// =================================================================
// Kernel 3: LayerNorm — one WARP per 256-elem row, no barriers.
//   8 floats/lane (2x LDG.128), shfl reduction, ddof=1, clamp 1e-6.
//   8 rows per 256-thread CTA -> grid 4096.
// =================================================================
__global__ __launch_bounds__(256) void layernorm_rows(
    float* __restrict__ out, const float* __restrict__ ln_w, const float* __restrict__ ln_b)
{
    const int warp = threadIdx.x >> 5;
    const int lane = threadIdx.x & 31;
    const size_t row = (size_t)blockIdx.x * 8 + warp;
    float* p = out + row * 256 + lane * 8;

    float4 v0 = *(const float4*)p;
    float4 v1 = *(const float4*)(p + 4);

    float s  = v0.x + v0.y + v0.z + v0.w + v1.x + v1.y + v1.z + v1.w;
    float ss = v0.x * v0.x + v0.y * v0.y + v0.z * v0.z + v0.w * v0.w +
               v1.x * v1.x + v1.y * v1.y + v1.z * v1.z + v1.w * v1.w;
#pragma unroll
    for (int o = 16; o > 0; o >>= 1) {
        s  += __shfl_xor_sync(0xffffffffu, s, o);
        ss += __shfl_xor_sync(0xffffffffu, ss, o);
    }

    const float mu  = s * (1.f / 256.f);
    float var = (ss - 256.f * mu * mu) * (1.f / 255.f);
    float sig = sqrtf(fmaxf(var, 0.f));
    sig = fmaxf(sig, 1e-6f);
    const float inv = 1.f / sig;

    const float4 w0 = *(const float4*)(ln_w + lane * 8);
    const float4 w1 = *(const float4*)(ln_w + lane * 8 + 4);
    const float4 b0 = *(const float4*)(ln_b + lane * 8);
    const float4 b1 = *(const float4*)(ln_b + lane * 8 + 4);

    float4 o0, o1;
    o0.x = (v0.x - mu) * inv * w0.x + b0.x;
    o0.y = (v0.y - mu) * inv * w0.y + b0.y;
    o0.z = (v0.z - mu) * inv * w0.z + b0.z;
    o0.w = (v0.w - mu) * inv * w0.w + b0.w;
    o1.x = (v1.x - mu) * inv * w1.x + b1.x;
    o1.y = (v1.y - mu) * inv * w1.y + b1.y;
    o1.z = (v1.z - mu) * inv * w1.z + b1.z;
    o1.w = (v1.w - mu) * inv * w1.w + b1.w;

    *(float4*)p       = o0;
    *(float4*)(p + 4) = o1;
}

// =================================================================
// launch
// =================================================================
extern "C" void kernel_launch(void* const* d_in, const int* in_sizes, int n_in,
                              void* d_out, int out_size)
{
    const float* x      = (const float*)d_in[0];
    const float* w_ih_f = (const float*)d_in[1];
    const float* w_hh_f = (const float*)d_in[2];
    const float* b_ih_f = (const float*)d_in[3];
    const float* b_hh_f = (const float*)d_in[4];
    const float* w_ih_b = (const float*)d_in[5];
    const float* w_hh_b = (const float*)d_in[6];
    const float* b_ih_b = (const float*)d_in[7];
    const float* b_hh_b = (const float*)d_in[8];
    const float* ln_w   = (const float*)d_in[9];
    const float* ln_b   = (const float*)d_in[10];
    float* out = (float*)d_out;

    static bool attrs_set = []() {
        cudaFuncSetAttribute(gemm_mma, cudaFuncAttributeMaxDynamicSharedMemorySize, GEMM_SMEM);
        return true;
    }();
    (void)attrs_set;

    conv_x<<<MROWS, 128>>>(x);
    conv_w<<<NTOT, 128>>>(w_ih_f, w_ih_b);

    dim3 ggrid(NTOT / 128, MROWS / 128);   // (6, 256)
    gemm_mma<<<ggrid, 256, GEMM_SMEM>>>(b_ih_f, b_ih_b);

    gru_scan<<<B_SZ * 2, 384>>>(w_hh_f, w_hh_b, b_hh_f, b_hh_b, out);

    layernorm_rows<<<MROWS / 8, 256>>>(out, ln_w, ln_b);
}

// round 17
// speedup vs baseline: 1.0690x; 1.0066x over previous
#include <cuda_runtime.h>
#include <cuda_fp16.h>
#include <math.h>
#include <stdint.h>

// ---------------- problem constants ----------------
#define B_SZ   64
#define T_SZ   512
#define D_IN   968
#define HID    128
#define G3     384
#define MROWS  (B_SZ * T_SZ)      // 32768
#define KPAD   1024
#define NTOT   768

// ---------------- scratch ----------------
__device__ float g_xp[2u * MROWS * G3];
__device__ __half g_abf[(size_t)MROWS * KPAD];
__device__ __half g_wbf[(size_t)NTOT * KPAD];

// ---------------- helpers ----------------
__device__ __forceinline__ uint32_t smem_u32(const void* p) {
    uint32_t a;
    asm("{ .reg .u64 t; cvta.to.shared.u64 t, %1; cvt.u32.u64 %0, t; }" : "=r"(a) : "l"(p));
    return a;
}
__device__ __forceinline__ void cp16(uint32_t dst, const void* src) {
    asm volatile("cp.async.cg.shared.global [%0], [%1], 16;" :: "r"(dst), "l"(src));
}
__device__ __forceinline__ void cp_commit() {
    asm volatile("cp.async.commit_group;" ::: "memory");
}
__device__ __forceinline__ void cp_wait1() {
    asm volatile("cp.async.wait_group 1;" ::: "memory");
}
__device__ __forceinline__ void ldmx4(uint32_t* r, uint32_t a) {
    asm volatile("ldmatrix.sync.aligned.m8n8.x4.shared.b16 {%0,%1,%2,%3}, [%4];"
                 : "=r"(r[0]), "=r"(r[1]), "=r"(r[2]), "=r"(r[3]) : "r"(a));
}
__device__ __forceinline__ void mma_f16(float* c, const uint32_t* a, const uint32_t* b) {
    asm volatile("mma.sync.aligned.m16n8k16.row.col.f32.f16.f16.f32 "
                 "{%0,%1,%2,%3}, {%4,%5,%6,%7}, {%8,%9}, {%0,%1,%2,%3};"
                 : "+f"(c[0]), "+f"(c[1]), "+f"(c[2]), "+f"(c[3])
                 : "r"(a[0]), "r"(a[1]), "r"(a[2]), "r"(a[3]), "r"(b[0]), "r"(b[1]));
}
__device__ __forceinline__ unsigned long long fma2(unsigned long long a,
                                                   unsigned long long b,
                                                   unsigned long long c) {
    unsigned long long d;
    asm("fma.rn.f32x2 %0, %1, %2, %3;" : "=l"(d) : "l"(a), "l"(b), "l"(c));
    return d;
}
__device__ __forceinline__ unsigned long long add2(unsigned long long a,
                                                   unsigned long long b) {
    unsigned long long d;
    asm("add.rn.f32x2 %0, %1, %2;" : "=l"(d) : "l"(a), "l"(b));
    return d;
}
__device__ __forceinline__ unsigned long long pack2(float x, float y) {
    float2 t = make_float2(x, y);
    return *(unsigned long long*)&t;
}
__device__ __forceinline__ float fast_sigmoid(float x) {
    return __fdividef(1.f, 1.f + __expf(-x));
}
__device__ __forceinline__ float fast_tanh(float y) {
    const float e = __expf(-2.f * fabsf(y));
    const float n = __fdividef(1.f - e, 1.f + e);
    return copysignf(n, y);
}

// =================================================================
// Kernel 0: fp32 -> fp16, x and w merged (KPAD=1024 unchanged).
//   blocks [0, MROWS)          -> x rows -> g_abf
//   blocks [MROWS, MROWS+NTOT) -> w rows -> g_wbf
// =================================================================
__global__ __launch_bounds__(128) void conv_all(const float* __restrict__ x,
                                                const float* __restrict__ w_f,
                                                const float* __restrict__ w_b) {
    const int rb = blockIdx.x;
    const float* src;
    __half* dst;
    if (rb < MROWS) {
        src = x + (size_t)rb * D_IN;
        dst = g_abf + (size_t)rb * KPAD;
    } else {
        const int n = rb - MROWS;
        src = (n < G3) ? (w_f + (size_t)n * D_IN) : (w_b + (size_t)(n - G3) * D_IN);
        dst = g_wbf + (size_t)n * KPAD;
    }
    const int k = threadIdx.x * 8;
    const float* s = src + k;
    __half2 h[4];
    if (k + 8 <= D_IN) {
        float4 v0 = *(const float4*)(s);
        float4 v1 = *(const float4*)(s + 4);
        h[0] = __floats2half2_rn(v0.x, v0.y);
        h[1] = __floats2half2_rn(v0.z, v0.w);
        h[2] = __floats2half2_rn(v1.x, v1.y);
        h[3] = __floats2half2_rn(v1.z, v1.w);
    } else {
        float t[8];
#pragma unroll
        for (int q = 0; q < 8; q++) t[q] = (k + q < D_IN) ? s[q] : 0.f;
        h[0] = __floats2half2_rn(t[0], t[1]);
        h[1] = __floats2half2_rn(t[2], t[3]);
        h[2] = __floats2half2_rn(t[4], t[5]);
        h[3] = __floats2half2_rn(t[6], t[7]);
    }
    *(uint4*)(dst + k) = *(uint4*)h;
}

// =================================================================
// Kernel 1: HMMA fp16 GEMM (R9/R14/R16 config — at HMMA floor).
//   M=32768, N=768, K=1024.  CTA 128x128x32, 8 warps, 3-stage
//   cp.async, single __syncthreads per stage, 2 CTAs/SM.
// =================================================================
#define BK      32
#define ROWB    80
#define ATILE   (128 * ROWB)
#define STAGEB  (2 * ATILE)
#define NSTG    32
#define GEMM_SMEM (3 * STAGEB)   // 61440

__global__ __launch_bounds__(256, 2) void gemm_mma(const float* __restrict__ bias_f,
                                                   const float* __restrict__ bias_b) {
    extern __shared__ char smem[];
    const uint32_t sb = smem_u32(smem);
    const int tid  = threadIdx.x;
    const int wid  = tid >> 5;
    const int lane = tid & 31;
    const int wrow = wid >> 2;
    const int wcol = wid & 3;

    const int m0 = blockIdx.y * 128;
    const int n0 = blockIdx.x * 128;

    const __half* Ag = g_abf + (size_t)m0 * KPAD;
    const __half* Bg = g_wbf + (size_t)n0 * KPAD;

    const int lrow  = tid >> 1;
    const int lseg0 = (tid & 1) * 2;

    float acc[4][4][4];
#pragma unroll
    for (int i = 0; i < 4; i++)
#pragma unroll
        for (int j = 0; j < 4; j++)
#pragma unroll
            for (int q = 0; q < 4; q++) acc[i][j][q] = 0.f;

    auto issue = [&](int s) {
        const int k0 = s * BK;
        const uint32_t st = sb + (s % 3) * STAGEB;
        const __half* arow = Ag + (size_t)lrow * KPAD + k0;
        const __half* brow = Bg + (size_t)lrow * KPAD + k0;
        cp16(st + lrow * ROWB + lseg0 * 16,        arow + lseg0 * 8);
        cp16(st + lrow * ROWB + (lseg0 + 1) * 16,  arow + (lseg0 + 1) * 8);
        cp16(st + ATILE + lrow * ROWB + lseg0 * 16,       brow + lseg0 * 8);
        cp16(st + ATILE + lrow * ROWB + (lseg0 + 1) * 16, brow + (lseg0 + 1) * 8);
    };

    issue(0); cp_commit();
    issue(1); cp_commit();

    const int a_r = (lane & 15);
    const int a_c = (lane >> 4) * 16;
    const int b_r = (lane & 7) + ((lane >> 4) << 3);
    const int b_c = ((lane >> 3) & 1) * 16;

    for (int s = 0; s < NSTG; s++) {
        cp_wait1();
        __syncthreads();   // all warps done with compute(s-1) = buffer (s+2)%3
        if (s + 2 < NSTG) issue(s + 2);
        cp_commit();

        const uint32_t st = sb + (s % 3) * STAGEB;
        const uint32_t aw = st + (wrow * 64 + a_r) * ROWB + a_c;
        const uint32_t bw = st + ATILE + (wcol * 32 + b_r) * ROWB + b_c;

#pragma unroll
        for (int kh = 0; kh < 2; kh++) {
            uint32_t afr[4][4], bfr[2][4];
#pragma unroll
            for (int mf = 0; mf < 4; mf++)
                ldmx4(afr[mf], aw + mf * 16 * ROWB + kh * 32);
#pragma unroll
            for (int np = 0; np < 2; np++)
                ldmx4(bfr[np], bw + np * 16 * ROWB + kh * 32);
#pragma unroll
            for (int mf = 0; mf < 4; mf++) {
#pragma unroll
                for (int nf = 0; nf < 4; nf++) {
                    uint32_t bp[2];
                    bp[0] = bfr[nf >> 1][(nf & 1) * 2 + 0];
                    bp[1] = bfr[nf >> 1][(nf & 1) * 2 + 1];
                    mma_f16(acc[mf][nf], afr[mf], bp);
                }
            }
        }
    }

    const int dir = (n0 >= G3) ? 1 : 0;
    const int gbase = n0 - dir * G3;
    const float* bias = dir ? bias_b : bias_f;

#pragma unroll
    for (int mf = 0; mf < 4; mf++) {
#pragma unroll
        for (int nf = 0; nf < 4; nf++) {
            const int g = gbase + wcol * 32 + nf * 8 + (lane & 3) * 2;
            const float bx = bias[g], by = bias[g + 1];
            const int r0 = m0 + wrow * 64 + mf * 16 + (lane >> 2);
            float* d0 = g_xp + ((size_t)dir * MROWS + r0) * G3 + g;
            float* d1 = d0 + (size_t)8 * G3;
            *(float2*)d0 = make_float2(acc[mf][nf][0] + bx, acc[mf][nf][1] + by);
            *(float2*)d1 = make_float2(acc[mf][nf][2] + bx, acc[mf][nf][3] + by);
        }
    }
}

// =================================================================
// Kernel 2: GRU scan — R6/R8/R14/R16 kernel (4-run-reproducible 355us).
// =================================================================
__global__ __launch_bounds__(384, 1) void gru_scan(
    const float* __restrict__ w_hh_f, const float* __restrict__ w_hh_b,
    const float* __restrict__ b_hh_f, const float* __restrict__ b_hh_b,
    float* __restrict__ out)
{
    __shared__ float4 h4s[32];            // h vector (float4 view)
    __shared__ float sR[128];             // sigmoid(r)
    __shared__ float sZ[128];             // sigmoid(z)

    const int j   = threadIdx.x;
    const int g   = j >> 7;               // 0=r 1=z 2=n
    const int i   = j & 127;
    const int dir = blockIdx.x & 1;
    const int b   = blockIdx.x >> 1;

    const float* __restrict__ w  = dir ? w_hh_b : w_hh_f;
    const float* __restrict__ bh = dir ? b_hh_b : b_hh_f;

    unsigned long long wp[64];
    const float4* wrow = (const float4*)(w + (size_t)j * HID);
#pragma unroll
    for (int q = 0; q < 32; q++) {
        float4 v = wrow[q];
        wp[2 * q]     = pack2(v.x, v.y);
        wp[2 * q + 1] = pack2(v.z, v.w);
    }
    const float bj = bh[j];
    if (j < 32) h4s[j] = make_float4(0.f, 0.f, 0.f, 0.f);
    __syncthreads();

    const float* xp_base  = g_xp + ((size_t)dir * MROWS + (size_t)b * T_SZ) * G3;
    float*       out_base = out + (size_t)b * T_SZ * 256 + dir * HID;
    const int t0 = dir ? (T_SZ - 1) : 0;
    const int tstep = dir ? -1 : 1;

    float hprev = 0.f;
    float gi0 = xp_base[(size_t)t0 * G3 + j];
    float gi1 = (T_SZ > 1) ? xp_base[(size_t)(t0 + tstep) * G3 + j] : 0.f;

    int t = t0;
    for (int s = 0; s < T_SZ; s++) {
        float gi2 = 0.f;
        if (s + 2 < T_SZ) gi2 = xp_base[(size_t)(t + 2 * tstep) * G3 + j];

        // ---- phase A: dot(w_j, h) via LDS.128 broadcast, 4 chains ----
        unsigned long long a0 = 0ull, a1 = 0ull, a2 = 0ull, a3 = 0ull;
#pragma unroll
        for (int q = 0; q < 8; q++) {
            float4 v0 = h4s[4 * q + 0];
            float4 v1 = h4s[4 * q + 1];
            float4 v2 = h4s[4 * q + 2];
            float4 v3 = h4s[4 * q + 3];
            a0 = fma2(wp[8 * q + 0], pack2(v0.x, v0.y), a0);
            a0 = fma2(wp[8 * q + 1], pack2(v0.z, v0.w), a0);
            a1 = fma2(wp[8 * q + 2], pack2(v1.x, v1.y), a1);
            a1 = fma2(wp[8 * q + 3], pack2(v1.z, v1.w), a1);
            a2 = fma2(wp[8 * q + 4], pack2(v2.x, v2.y), a2);
            a2 = fma2(wp[8 * q + 5], pack2(v2.z, v2.w), a2);
            a3 = fma2(wp[8 * q + 6], pack2(v3.x, v3.y), a3);
            a3 = fma2(wp[8 * q + 7], pack2(v3.z, v3.w), a3);
        }
        a0 = add2(a0, a1);
        a2 = add2(a2, a3);
        a0 = add2(a0, a2);
        float2 ap = *(float2*)&a0;
        const float accv = ap.x + ap.y + bj;

        if (g == 0)      sR[i] = fast_sigmoid(accv + gi0);
        else if (g == 1) sZ[i] = fast_sigmoid(accv + gi0);
        // g==2 keeps gh_n=accv, gi_n=gi0 in registers

        __syncthreads();

        // ---- phase B: n-gate group updates h ----
        if (g == 2) {
            const float r = sR[i];
            const float z = sZ[i];
            const float n = fast_tanh(fmaf(r, accv, gi0));
            const float hn = fmaf(z, hprev - n, n);
            hprev = hn;
            ((float*)h4s)[i] = hn;
            out_base[(size_t)t * 256 + i] = hn;
        }
        __syncthreads();

        gi0 = gi1;
        gi1 = gi2;
        t += tstep;
    }
}

// =================================================================
// Kernel 3: LayerNorm — one WARP per 256-elem row (R16, measured).
// =================================================================
__global__ __launch_bounds__(256) void layernorm_rows(
    float* __restrict__ out, const float* __restrict__ ln_w, const float* __restrict__ ln_b)
{
    const int warp = threadIdx.x >> 5;
    const int lane = threadIdx.x & 31;
    const size_t row = (size_t)blockIdx.x * 8 + warp;
    float* p = out + row * 256 + lane * 8;

    float4 v0 = *(const float4*)p;
    float4 v1 = *(const float4*)(p + 4);

    float s  = v0.x + v0.y + v0.z + v0.w + v1.x + v1.y + v1.z + v1.w;
    float ss = v0.x * v0.x + v0.y * v0.y + v0.z * v0.z + v0.w * v0.w +
               v1.x * v1.x + v1.y * v1.y + v1.z * v1.z + v1.w * v1.w;
#pragma unroll
    for (int o = 16; o > 0; o >>= 1) {
        s  += __shfl_xor_sync(0xffffffffu, s, o);
        ss += __shfl_xor_sync(0xffffffffu, ss, o);
    }

    const float mu  = s * (1.f / 256.f);
    float var = (ss - 256.f * mu * mu) * (1.f / 255.f);
    float sig = sqrtf(fmaxf(var, 0.f));
    sig = fmaxf(sig, 1e-6f);
    const float inv = 1.f / sig;

    const float4 w0 = *(const float4*)(ln_w + lane * 8);
    const float4 w1 = *(const float4*)(ln_w + lane * 8 + 4);
    const float4 b0 = *(const float4*)(ln_b + lane * 8);
    const float4 b1 = *(const float4*)(ln_b + lane * 8 + 4);

    float4 o0, o1;
    o0.x = (v0.x - mu) * inv * w0.x + b0.x;
    o0.y = (v0.y - mu) * inv * w0.y + b0.y;
    o0.z = (v0.z - mu) * inv * w0.z + b0.z;
    o0.w = (v0.w - mu) * inv * w0.w + b0.w;
    o1.x = (v1.x - mu) * inv * w1.x + b1.x;
    o1.y = (v1.y - mu) * inv * w1.y + b1.y;
    o1.z = (v1.z - mu) * inv * w1.z + b1.z;
    o1.w = (v1.w - mu) * inv * w1.w + b1.w;

    *(float4*)p       = o0;
    *(float4*)(p + 4) = o1;
}

// =================================================================
// launch
// =================================================================
extern "C" void kernel_launch(void* const* d_in, const int* in_sizes, int n_in,
                              void* d_out, int out_size)
{
    const float* x      = (const float*)d_in[0];
    const float* w_ih_f = (const float*)d_in[1];
    const float* w_hh_f = (const float*)d_in[2];
    const float* b_ih_f = (const float*)d_in[3];
    const float* b_hh_f = (const float*)d_in[4];
    const float* w_ih_b = (const float*)d_in[5];
    const float* w_hh_b = (const float*)d_in[6];
    const float* b_ih_b = (const float*)d_in[7];
    const float* b_hh_b = (const float*)d_in[8];
    const float* ln_w   = (const float*)d_in[9];
    const float* ln_b   = (const float*)d_in[10];
    float* out = (float*)d_out;

    static bool attrs_set = []() {
        cudaFuncSetAttribute(gemm_mma, cudaFuncAttributeMaxDynamicSharedMemorySize, GEMM_SMEM);
        return true;
    }();
    (void)attrs_set;

    conv_all<<<MROWS + NTOT, 128>>>(x, w_ih_f, w_ih_b);

    dim3 ggrid(NTOT / 128, MROWS / 128);   // (6, 256)
    gemm_mma<<<ggrid, 256, GEMM_SMEM>>>(b_ih_f, b_ih_b);

    gru_scan<<<B_SZ * 2, 384>>>(w_hh_f, w_hh_b, b_hh_f, b_hh_b, out);

    layernorm_rows<<<MROWS / 8, 256>>>(out, ln_w, ln_b);
}